// round 15
// baseline (speedup 1.0000x reference)
#include <cuda_runtime.h>
#include <cuda_fp16.h>
#include <cstdint>
#include <cstddef>

#define NPATCH 12544
#define PD     3840
#define PROJ   768
#define TOKN   9633792ULL

__device__ float2 g_stats[NPATCH];
__device__ float  g_u[PROJ];
__device__ float  g_v[PROJ];
__device__ __half g_Ah[(size_t)NPATCH * PD];   // fp16 copy of patches
__device__ __half g_Wh[(size_t)PD * PROJ];     // fp16(gamma[k] * W[k][e])

// ---------------- zero u/v ----------------
__global__ void zero_uv_kernel() {
    int t = threadIdx.x;
    if (t < PROJ) { g_u[t] = 0.f; g_v[t] = 0.f; }
}

// ---------------- fused prep: u/v column sums + gamma-scaled fp16 W ----------------
__global__ void prep_kernel(const float* __restrict__ W, const float* __restrict__ gamma,
                            const float* __restrict__ beta) {
    int e = blockIdx.x * 256 + threadIdx.x;
    int d0 = blockIdx.y * 240;
    float u = 0.f, v = 0.f;
#pragma unroll 4
    for (int d = d0; d < d0 + 240; ++d) {
        float w = W[(size_t)d * PROJ + e];
        float g = gamma[d];
        float wg = w * g;
        u += wg;
        v += beta[d] * w;
        g_Wh[(size_t)d * PROJ + e] = __float2half_rn(wg);
    }
    atomicAdd(&g_u[e], u);
    atomicAdd(&g_v[e], v);
}

// ---------------- patch extraction ----------------
__global__ __launch_bounds__(256)
void patch_kernel(const float* __restrict__ img, float* __restrict__ patches) {
    __shared__ float sv[PD];
    __shared__ float rs[16];

    int p = blockIdx.x;
    int b = p / 196;
    int pg = p - b * 196;
    int gy = pg / 14, gx = pg - (pg / 14) * 14;
    int t = threadIdx.x;

    const int py = t >> 4, px = t & 15;
    const int hb = gy * 16 + py;
    const int wb = gx * 16 + px;
    const int ibase = ((b * 224 + hb) * 224 + wb) * 3;

    const int DH[5] = {0, 8, -8, 8, -8};
    const int DW[5] = {0, 8,  8, -8, -8};

    float s = 0.f, ss = 0.f;
#pragma unroll
    for (int j = 0; j < 15; ++j) {
        const int g = j / 3;
        const int c = j - g * 3;
        const int dh = DH[g], dw = DW[g];
        int h = hb + dh, w = wb + dw;
        float v = 0.f;
        if ((unsigned)h < 224u && (unsigned)w < 224u)
            v = img[ibase + (dh * 224 + dw) * 3 + c];
        sv[t * 15 + j] = v;
        s += v; ss += v * v;
    }
    __syncthreads();

    float*  dst  = patches + (size_t)p * PD;
    __half* dsth = g_Ah   + (size_t)p * PD;
#pragma unroll
    for (int j = 0; j < 15; ++j) {
        float v = sv[t + j * 256];
        dst[t + j * 256]  = v;
        dsth[t + j * 256] = __float2half_rn(v);
    }

#pragma unroll
    for (int o = 16; o > 0; o >>= 1) {
        s  += __shfl_xor_sync(0xffffffffu, s, o);
        ss += __shfl_xor_sync(0xffffffffu, ss, o);
    }
    int warp = t >> 5, lane = t & 31;
    if (lane == 0) { rs[warp] = s; rs[8 + warp] = ss; }
    __syncthreads();
    if (t == 0) {
        float S = 0.f, SS = 0.f;
#pragma unroll
        for (int w2 = 0; w2 < 8; ++w2) { S += rs[w2]; SS += rs[8 + w2]; }
        float mean = S * (1.f / PD);
        float var = SS * (1.f / PD) - mean * mean;
        g_stats[p] = make_float2(mean, rsqrtf(var + 1e-6f));
    }
}

// ---------------- GEMM: fp16 mma.sync + cp.async.bulk, 256 thr, occ 2, BK=64, 3-stage ----------------
#define BM 128
#define BN 128
#define BK 64
#define KITERS 60
#define STAGES 3
#define LDA_H 72      // 144B/row; conflict-free ldmatrix
#define LDB_H 136     // 272B/row; conflict-free
#define SA_BYTES (BM * LDA_H * 2)     // 18432
#define SB_BYTES (BK * LDB_H * 2)     // 17408
#define STAGE_BYTES (SA_BYTES + SB_BYTES)    // 35840
#define MBAR_OFF (STAGES * STAGE_BYTES)      // 107520
#define SMEM_BYTES (MBAR_OFF + 64)
#define STAGE_TX 32768u                      // A 128*128 + B 64*256 bytes

__device__ __forceinline__ uint32_t sptr(const void* p) {
    uint32_t a;
    asm("{ .reg .u64 t; cvta.to.shared.u64 t, %1; cvt.u32.u64 %0, t; }" : "=r"(a) : "l"(p));
    return a;
}

#define MBAR_INIT(addr, cnt) \
    asm volatile("mbarrier.init.shared.b64 [%0], %1;" :: "r"(addr), "r"((uint32_t)(cnt)) : "memory")
#define MBAR_EXPECT_TX(addr, bytes) \
    asm volatile("mbarrier.arrive.expect_tx.shared.b64 _, [%0], %1;" :: "r"(addr), "r"((uint32_t)(bytes)) : "memory")
#define BULK_CP(dst_u32, src, sz, mbar) \
    asm volatile("cp.async.bulk.shared::cta.global.mbarrier::complete_tx::bytes [%0], [%1], %2, [%3];" \
                 :: "r"(dst_u32), "l"(src), "r"((uint32_t)(sz)), "r"(mbar) : "memory")

#define MBAR_WAIT(addr, par) do { \
    uint32_t _m = (addr), _p = (par), _d; \
    asm volatile("{\n\t.reg .pred p;\n\t" \
        "mbarrier.try_wait.parity.acquire.cta.shared::cta.b64 p, [%1], %2;\n\t" \
        "selp.b32 %0, 1, 0, p;\n\t}" : "=r"(_d) : "r"(_m), "r"(_p) : "memory"); \
    if (!_d) { \
        asm volatile("{\n\t.reg .pred P1;\n\t" \
            "WL_%=:\n\t" \
            "mbarrier.try_wait.parity.acquire.cta.shared::cta.b64 P1, [%0], %1, 0x989680;\n\t" \
            "@P1 bra.uni WD_%=;\n\t" \
            "bra.uni WL_%=;\n\t" \
            "WD_%=:\n\t}" :: "r"(_m), "r"(_p) : "memory"); \
    } \
} while (0)

#define LDSM4(r0, r1, r2, r3, a) \
    asm volatile("ldmatrix.sync.aligned.m8n8.x4.shared.b16 {%0,%1,%2,%3}, [%4];" \
                 : "=r"(r0), "=r"(r1), "=r"(r2), "=r"(r3) : "r"(a))
#define LDSM4T(r0, r1, r2, r3, a) \
    asm volatile("ldmatrix.sync.aligned.m8n8.x4.trans.shared.b16 {%0,%1,%2,%3}, [%4];" \
                 : "=r"(r0), "=r"(r1), "=r"(r2), "=r"(r3) : "r"(a))

#define MMA16(C, A_, b0_, b1_) \
    asm volatile("mma.sync.aligned.m16n8k16.row.col.f32.f16.f16.f32 " \
                 "{%0,%1,%2,%3},{%4,%5,%6,%7},{%8,%9},{%0,%1,%2,%3};" \
                 : "+f"((C)[0]), "+f"((C)[1]), "+f"((C)[2]), "+f"((C)[3]) \
                 : "r"((A_)[0]), "r"((A_)[1]), "r"((A_)[2]), "r"((A_)[3]), \
                   "r"(b0_), "r"(b1_))

__global__ __launch_bounds__(256, 2)
void gemm_kernel(const float* __restrict__ bbias, float* __restrict__ out) {
    extern __shared__ char smem[];
    const uint32_t smem_base = sptr(smem);

    const int m0 = blockIdx.x * BM;
    const int n0 = blockIdx.y * BN;
    const int t = threadIdx.x;
    const int warp = t >> 5, lane = t & 31;
    const int wm = warp >> 1, wn = warp & 1;     // 4m x 2n grid of 32x64 warp tiles
    const int gid = lane >> 2, tig = lane & 3;

    float c[2][8][4];
#pragma unroll
    for (int i = 0; i < 2; ++i)
#pragma unroll
        for (int j = 0; j < 8; ++j)
#pragma unroll
            for (int q = 0; q < 4; ++q) c[i][j][q] = 0.f;

    const __half* Ap = g_Ah + (size_t)m0 * PD;
    const __half* Bp = g_Wh + n0;

    auto mb = [&](int s) -> uint32_t { return smem_base + MBAR_OFF + s * 8; };

    // one bulk per tile row: t<128 -> A row t (128B); t in [128,192) -> B row t-128 (256B)
    auto issue_stage = [&](int s, int stage_it) {
        const int k0 = stage_it * BK;
        if (t < 128) {
            BULK_CP(smem_base + s * STAGE_BYTES + t * (LDA_H * 2),
                    (const void*)(Ap + (size_t)t * PD + k0), 128, mb(s));
        } else if (t < 192) {
            int r = t - 128;
            BULK_CP(smem_base + s * STAGE_BYTES + SA_BYTES + r * (LDB_H * 2),
                    (const void*)(Bp + (size_t)(k0 + r) * PROJ), 256, mb(s));
        }
    };

    const int jmat = lane >> 3;
    const int rrow = lane & 7;

    auto compute = [&](int s) {
        const uint32_t sa = smem_base + s * STAGE_BYTES;
        const uint32_t sb = sa + SA_BYTES;
#pragma unroll
        for (int kk = 0; kk < 4; ++kk) {
            const int kb = kk * 16;
            uint32_t af[2][4];
#pragma unroll
            for (int i = 0; i < 2; ++i) {
                int row = wm * 32 + i * 16 + (jmat & 1) * 8 + rrow;
                int col = kb + (jmat >> 1) * 8;
                LDSM4(af[i][0], af[i][1], af[i][2], af[i][3],
                      sa + row * (LDA_H * 2) + col * 2);
            }
#pragma unroll
            for (int p = 0; p < 4; ++p) {
                uint32_t b0, b1, b2, b3;
                int row = kb + (jmat & 1) * 8 + rrow;
                int col = wn * 64 + p * 16 + (jmat >> 1) * 8;
                LDSM4T(b0, b1, b2, b3, sb + row * (LDB_H * 2) + col * 2);
#pragma unroll
                for (int i = 0; i < 2; ++i) {
                    MMA16(c[i][2 * p],     af[i], b0, b1);
                    MMA16(c[i][2 * p + 1], af[i], b2, b3);
                }
            }
        }
    };

    // prologue: init barriers, prefetch stages 0 and 1
    if (t == 0) {
#pragma unroll
        for (int s = 0; s < STAGES; ++s) MBAR_INIT(mb(s), 1);
    }
    __syncthreads();
    if (t == 0) {
        MBAR_EXPECT_TX(mb(0), STAGE_TX);
        MBAR_EXPECT_TX(mb(1), STAGE_TX);
    }
    __syncthreads();
    issue_stage(0, 0);
    issue_stage(1, 1);

    for (int it = 0; it < KITERS; ++it) {
        const int s = it % STAGES;
        MBAR_WAIT(mb(s), (uint32_t)((it / STAGES) & 1));
        if (it + 2 < KITERS && t == 0)
            MBAR_EXPECT_TX(mb((it + 2) % STAGES), STAGE_TX);
        __syncthreads();   // orders expect_tx before issues; protects slot reuse
        if (it + 2 < KITERS) issue_stage((it + 2) % STAGES, it + 2);
        compute(s);
    }

    // epilogue: token = rstd*S + (-rstd*mean)*u + (v + b)
    float ue[8][2], vb[8][2];
#pragma unroll
    for (int j = 0; j < 8; ++j) {
        int e = n0 + wn * 64 + j * 8 + tig * 2;
        ue[j][0] = g_u[e];     ue[j][1] = g_u[e + 1];
        vb[j][0] = g_v[e] + bbias[e];
        vb[j][1] = g_v[e + 1] + bbias[e + 1];
    }
#pragma unroll
    for (int i = 0; i < 2; ++i) {
        int mrow = m0 + wm * 32 + i * 16 + gid;
        float2 s0 = g_stats[mrow];
        float2 s1 = g_stats[mrow + 8];
        float r0 = s0.y, mm0 = -s0.x * s0.y;
        float r1 = s1.y, mm1 = -s1.x * s1.y;
#pragma unroll
        for (int j = 0; j < 8; ++j) {
            int e = n0 + wn * 64 + j * 8 + tig * 2;
            float* o0 = out + (size_t)mrow * PROJ + e;
            float* o1 = out + (size_t)(mrow + 8) * PROJ + e;
            o0[0] = r0 * c[i][j][0] + mm0 * ue[j][0] + vb[j][0];
            o0[1] = r0 * c[i][j][1] + mm0 * ue[j][1] + vb[j][1];
            o1[0] = r1 * c[i][j][2] + mm1 * ue[j][0] + vb[j][0];
            o1[1] = r1 * c[i][j][3] + mm1 * ue[j][1] + vb[j][1];
        }
    }
}

// ---------------- launch ----------------
extern "C" void kernel_launch(void* const* d_in, const int* in_sizes, int n_in,
                              void* d_out, int out_size) {
    const float* images = (const float*)d_in[0];
    const float* gamma  = (const float*)d_in[1];
    const float* beta   = (const float*)d_in[2];
    const float* W      = (const float*)d_in[3];
    const float* b      = (const float*)d_in[4];
    float* out = (float*)d_out;
    float* tokens  = out;
    float* patches = out + TOKN;

    // 4 launches; ncu capture slot (4th) = gemm_kernel
    zero_uv_kernel<<<1, 768>>>();
    prep_kernel<<<dim3(3, 16), 256>>>(W, gamma, beta);
    patch_kernel<<<NPATCH, 256>>>(images, patches);

    static bool configured = false;
    if (!configured) {
        cudaFuncSetAttribute(gemm_kernel, cudaFuncAttributeMaxDynamicSharedMemorySize, SMEM_BYTES);
        configured = true;
    }
    gemm_kernel<<<dim3(98, 6), 256, SMEM_BYTES>>>(b, tokens);
}

// round 16
// speedup vs baseline: 1.1935x; 1.1935x over previous
#include <cuda_runtime.h>
#include <cuda_fp16.h>
#include <cstdint>
#include <cstddef>

#define NPATCH 12544
#define PD     3840
#define PROJ   768
#define TOKN   9633792ULL
#define PREP_BLOCKS 48

__device__ float2 g_stats[NPATCH];
__device__ float  g_up[16 * PROJ];             // per-slab partial u
__device__ float  g_vp[16 * PROJ];             // per-slab partial v
__device__ __half g_Ah[(size_t)NPATCH * PD];   // fp16 copy of patches
__device__ __half g_Wh[(size_t)PD * PROJ];     // fp16(gamma[k] * W[k][e])

// ---------------- fused: W-prep (blocks 0..47) + patch extraction (blocks 48+) ----------------
__global__ __launch_bounds__(256)
void fused_pp_kernel(const float* __restrict__ img, float* __restrict__ patches,
                     const float* __restrict__ W, const float* __restrict__ gamma,
                     const float* __restrict__ beta) {
    const int bid = blockIdx.x;
    const int t = threadIdx.x;

    if (bid < PREP_BLOCKS) {
        // prep: u/v partial column sums + gamma-scaled fp16 W
        int e = (bid % 3) * 256 + t;
        int slab = bid / 3;
        int d0 = slab * 240;
        float u = 0.f, v = 0.f;
#pragma unroll 4
        for (int d = d0; d < d0 + 240; ++d) {
            float w = W[(size_t)d * PROJ + e];
            float g = gamma[d];
            float wg = w * g;
            u += wg;
            v += beta[d] * w;
            g_Wh[(size_t)d * PROJ + e] = __float2half_rn(wg);
        }
        g_up[slab * PROJ + e] = u;
        g_vp[slab * PROJ + e] = v;
        return;
    }

    // patch extraction
    __shared__ float sv[PD];
    __shared__ float rs[16];

    int p = bid - PREP_BLOCKS;
    int b = p / 196;
    int pg = p - b * 196;
    int gy = pg / 14, gx = pg - (pg / 14) * 14;

    const int py = t >> 4, px = t & 15;
    const int hb = gy * 16 + py;
    const int wb = gx * 16 + px;
    const int ibase = ((b * 224 + hb) * 224 + wb) * 3;

    const int DH[5] = {0, 8, -8, 8, -8};
    const int DW[5] = {0, 8,  8, -8, -8};

    float s = 0.f, ss = 0.f;
#pragma unroll
    for (int j = 0; j < 15; ++j) {
        const int g = j / 3;
        const int c = j - g * 3;
        const int dh = DH[g], dw = DW[g];
        int h = hb + dh, w = wb + dw;
        float v = 0.f;
        if ((unsigned)h < 224u && (unsigned)w < 224u)
            v = img[ibase + (dh * 224 + dw) * 3 + c];
        sv[t * 15 + j] = v;
        s += v; ss += v * v;
    }
    __syncthreads();

    float*  dst  = patches + (size_t)p * PD;
    __half* dsth = g_Ah   + (size_t)p * PD;
#pragma unroll
    for (int j = 0; j < 15; ++j) {
        float v = sv[t + j * 256];
        dst[t + j * 256]  = v;
        dsth[t + j * 256] = __float2half_rn(v);
    }

#pragma unroll
    for (int o = 16; o > 0; o >>= 1) {
        s  += __shfl_xor_sync(0xffffffffu, s, o);
        ss += __shfl_xor_sync(0xffffffffu, ss, o);
    }
    int warp = t >> 5, lane = t & 31;
    if (lane == 0) { rs[warp] = s; rs[8 + warp] = ss; }
    __syncthreads();
    if (t == 0) {
        float S = 0.f, SS = 0.f;
#pragma unroll
        for (int w2 = 0; w2 < 8; ++w2) { S += rs[w2]; SS += rs[8 + w2]; }
        float mean = S * (1.f / PD);
        float var = SS * (1.f / PD) - mean * mean;
        g_stats[p] = make_float2(mean, rsqrtf(var + 1e-6f));
    }
}

// ---------------- GEMM: fp16 mma.sync, 256 threads, occ 2, BK=64, 3-stage (R13 config) ----------------
#define BM 128
#define BN 128
#define BK 64
#define KITERS 60
#define STAGES 3
#define LDA_H 72      // 144B/row; conflict-free ldmatrix
#define LDB_H 136     // 272B/row; conflict-free
#define SA_BYTES (BM * LDA_H * 2)     // 18432
#define SB_BYTES (BK * LDB_H * 2)     // 17408
#define STAGE_BYTES (SA_BYTES + SB_BYTES)    // 35840
#define SMEM_BYTES (STAGES * STAGE_BYTES)    // 107520

__device__ __forceinline__ uint32_t sptr(const void* p) {
    uint32_t a;
    asm("{ .reg .u64 t; cvta.to.shared.u64 t, %1; cvt.u32.u64 %0, t; }" : "=r"(a) : "l"(p));
    return a;
}
#define CP16(dst_u32, src) asm volatile("cp.async.cg.shared.global [%0], [%1], 16;" :: "r"(dst_u32), "l"(src))

#define LDSM4(r0, r1, r2, r3, a) \
    asm volatile("ldmatrix.sync.aligned.m8n8.x4.shared.b16 {%0,%1,%2,%3}, [%4];" \
                 : "=r"(r0), "=r"(r1), "=r"(r2), "=r"(r3) : "r"(a))
#define LDSM4T(r0, r1, r2, r3, a) \
    asm volatile("ldmatrix.sync.aligned.m8n8.x4.trans.shared.b16 {%0,%1,%2,%3}, [%4];" \
                 : "=r"(r0), "=r"(r1), "=r"(r2), "=r"(r3) : "r"(a))

#define MMA16(C, A_, b0_, b1_) \
    asm volatile("mma.sync.aligned.m16n8k16.row.col.f32.f16.f16.f32 " \
                 "{%0,%1,%2,%3},{%4,%5,%6,%7},{%8,%9},{%0,%1,%2,%3};" \
                 : "+f"((C)[0]), "+f"((C)[1]), "+f"((C)[2]), "+f"((C)[3]) \
                 : "r"((A_)[0]), "r"((A_)[1]), "r"((A_)[2]), "r"((A_)[3]), \
                   "r"(b0_), "r"(b1_))

__global__ __launch_bounds__(256, 2)
void gemm_kernel(const float* __restrict__ bbias, float* __restrict__ out) {
    extern __shared__ char smem[];
    const uint32_t smem_base = sptr(smem);

    const int m0 = blockIdx.x * BM;
    const int n0 = blockIdx.y * BN;
    const int t = threadIdx.x;
    const int warp = t >> 5, lane = t & 31;
    const int wm = warp >> 1, wn = warp & 1;     // 4m x 2n grid of 32x64 warp tiles
    const int gid = lane >> 2, tig = lane & 3;

    float c[2][8][4];
#pragma unroll
    for (int i = 0; i < 2; ++i)
#pragma unroll
        for (int j = 0; j < 8; ++j)
#pragma unroll
            for (int q = 0; q < 4; ++q) c[i][j][q] = 0.f;

    const __half* Ap = g_Ah + (size_t)m0 * PD;
    const __half* Bp = g_Wh + n0;

    auto load_stage = [&](int s, int it) {
        const int k0 = it * BK;
        const uint32_t sa = smem_base + s * STAGE_BYTES;
        const uint32_t sb = sa + SA_BYTES;
#pragma unroll
        for (int q = 0; q < 4; ++q) {
            int cid = q * 256 + t;
            int row = cid >> 3, c8 = cid & 7;
            CP16(sa + row * (LDA_H * 2) + c8 * 16,
                 Ap + (size_t)row * PD + k0 + c8 * 8);
        }
#pragma unroll
        for (int q = 0; q < 4; ++q) {
            int cid = q * 256 + t;
            int row = cid >> 4, c16 = cid & 15;
            CP16(sb + row * (LDB_H * 2) + c16 * 16,
                 Bp + (size_t)(k0 + row) * PROJ + c16 * 8);
        }
        asm volatile("cp.async.commit_group;");
    };

    const int jmat = lane >> 3;
    const int rrow = lane & 7;

    auto compute = [&](int s) {
        const uint32_t sa = smem_base + s * STAGE_BYTES;
        const uint32_t sb = sa + SA_BYTES;
#pragma unroll
        for (int kk = 0; kk < 4; ++kk) {
            const int kb = kk * 16;
            uint32_t af[2][4];
#pragma unroll
            for (int i = 0; i < 2; ++i) {
                int row = wm * 32 + i * 16 + (jmat & 1) * 8 + rrow;
                int col = kb + (jmat >> 1) * 8;
                LDSM4(af[i][0], af[i][1], af[i][2], af[i][3],
                      sa + row * (LDA_H * 2) + col * 2);
            }
#pragma unroll
            for (int p = 0; p < 4; ++p) {
                uint32_t b0, b1, b2, b3;
                int row = kb + (jmat & 1) * 8 + rrow;
                int col = wn * 64 + p * 16 + (jmat >> 1) * 8;
                LDSM4T(b0, b1, b2, b3, sb + row * (LDB_H * 2) + col * 2);
#pragma unroll
                for (int i = 0; i < 2; ++i) {
                    MMA16(c[i][2 * p],     af[i], b0, b1);
                    MMA16(c[i][2 * p + 1], af[i], b2, b3);
                }
            }
        }
    };

    load_stage(0, 0);
    load_stage(1, 1);

    for (int it = 0; it < KITERS; ++it) {
        if (it + 2 < KITERS) asm volatile("cp.async.wait_group 1;");
        else                 asm volatile("cp.async.wait_group 0;");
        __syncthreads();
        if (it + 2 < KITERS) load_stage((it + 2) % STAGES, it + 2);
        compute(it % STAGES);
    }

    // epilogue: reduce u/v partials into smem (reuse stage buffers), then fuse LN affine
    __syncthreads();
    float* su  = (float*)smem;           // [BN]
    float* svb = su + BN;                // [BN]
    if (t < BN) {
        float uu = 0.f, vv = 0.f;
#pragma unroll
        for (int s2 = 0; s2 < 16; ++s2) {
            uu += g_up[s2 * PROJ + n0 + t];
            vv += g_vp[s2 * PROJ + n0 + t];
        }
        su[t]  = uu;
        svb[t] = vv + bbias[n0 + t];
    }
    __syncthreads();

    float ue[8][2], vb[8][2];
#pragma unroll
    for (int j = 0; j < 8; ++j) {
        int e = wn * 64 + j * 8 + tig * 2;
        ue[j][0] = su[e];      ue[j][1] = su[e + 1];
        vb[j][0] = svb[e];     vb[j][1] = svb[e + 1];
    }
#pragma unroll
    for (int i = 0; i < 2; ++i) {
        int mrow = m0 + wm * 32 + i * 16 + gid;
        float2 s0 = g_stats[mrow];
        float2 s1 = g_stats[mrow + 8];
        float r0 = s0.y, mm0 = -s0.x * s0.y;
        float r1 = s1.y, mm1 = -s1.x * s1.y;
#pragma unroll
        for (int j = 0; j < 8; ++j) {
            int e = n0 + wn * 64 + j * 8 + tig * 2;
            float* o0 = out + (size_t)mrow * PROJ + e;
            float* o1 = out + (size_t)(mrow + 8) * PROJ + e;
            o0[0] = r0 * c[i][j][0] + mm0 * ue[j][0] + vb[j][0];
            o0[1] = r0 * c[i][j][1] + mm0 * ue[j][1] + vb[j][1];
            o1[0] = r1 * c[i][j][2] + mm1 * ue[j][0] + vb[j][0];
            o1[1] = r1 * c[i][j][3] + mm1 * ue[j][1] + vb[j][1];
        }
    }
}

// ---------------- launch ----------------
extern "C" void kernel_launch(void* const* d_in, const int* in_sizes, int n_in,
                              void* d_out, int out_size) {
    const float* images = (const float*)d_in[0];
    const float* gamma  = (const float*)d_in[1];
    const float* beta   = (const float*)d_in[2];
    const float* W      = (const float*)d_in[3];
    const float* b      = (const float*)d_in[4];
    float* out = (float*)d_out;
    float* tokens  = out;
    float* patches = out + TOKN;

    fused_pp_kernel<<<NPATCH + PREP_BLOCKS, 256>>>(images, patches, W, gamma, beta);

    static bool configured = false;
    if (!configured) {
        cudaFuncSetAttribute(gemm_kernel, cudaFuncAttributeMaxDynamicSharedMemorySize, SMEM_BYTES);
        configured = true;
    }
    gemm_kernel<<<dim3(98, 6), 256, SMEM_BYTES>>>(b, tokens);
}